// round 7
// baseline (speedup 1.0000x reference)
#include <cuda_runtime.h>

#define D 2048
#define B 16

#define NGBLK 64       // gates blocks (4 items each, staggered slice production)
#define WGRID 2048     // writer blocks: 16 slices x 16 batches x 8 row-chunks

// Scratch + sync state (allocation-free rule: device globals, zero-init)
__device__ float    g_u[B * D];
__device__ float    g_diag[B * D];
__device__ unsigned g_ready[16];
__device__ unsigned g_done;

__device__ __forceinline__ float sigmoidf(float x) {
    return 1.0f / (1.0f + __expf(-x));
}

// Warp transpose-reduce: lane l ends with (in v[0]) the 32-lane total of
// logical index l.
__device__ __forceinline__ void treduce32(float (&v)[32], int lane) {
#pragma unroll
    for (int m = 16; m > 0; m >>= 1) {
#pragma unroll
        for (int t = 0; t < 16; t++) {
            if (t < m) {
                float lo = v[t];
                float hi = v[t + m];
                float send = (lane & m) ? lo : hi;
                float recv = __shfl_xor_sync(0xffffffffu, send, m);
                v[t] = (lane & m) ? (hi + recv) : (lo + recv);
            }
        }
    }
}

__device__ __forceinline__ void finalize_one(
    int b, int i, float dA, float dX,
    const float* __restrict__ xt, const float* __restrict__ h,
    const float* __restrict__ ba, const float* __restrict__ bx,
    const float* __restrict__ Lam)
{
    float rt = sigmoidf(dA + __ldg(ba + i));
    float it = sigmoidf(dX + __ldg(bx + i));
    float la = -log1pf(__expf(-__ldg(Lam + i)));   // -softplus(-Lam)
    float t  = la * rt * 0.125f;                   // /C, C=8
    float a  = __expf(t);
    float om = -expm1f(2.0f * t);                  // 1 - a^2, cancellation-free
    float u  = sqrtf(fmaxf(om, 0.0f)) * it * __ldg(xt + b * D + i);
    g_u[b * D + i]    = u;
    g_diag[b * D + i] = a * __ldg(h + b * D + i);
}

// One gates item = 8 columns [ibase, ibase+8) x both matrices x all batches.
__device__ void gates_item(
    int ibase, int tid, float4* xs4,
    const float* __restrict__ xt, const float* __restrict__ h,
    const float* __restrict__ Wa, const float* __restrict__ Wx,
    const float* __restrict__ ba, const float* __restrict__ bx,
    const float* __restrict__ Lam)
{
    const int lane = tid & 31;
    const int warp = tid >> 5;
    const int bg   = warp >> 2;
    const int i0   = ibase + (warp & 3) * 2;
    const int i1   = i0 + 1;

    // [0..7]=dotA(i0,b), [8..15]=dotX(i0,b), [16..23]=dotA(i1,b), [24..31]=dotX(i1,b)
    float v[32];
#pragma unroll
    for (int t = 0; t < 32; t++) v[t] = 0.0f;

    const float4* xt4 = reinterpret_cast<const float4*>(xt);

#pragma unroll 1
    for (int kt = 0; kt < D; kt += 512) {
        __syncthreads();
#pragma unroll
        for (int e = tid; e < B * 128; e += 256) {
            int b = e >> 7, c = e & 127;
            xs4[e] = xt4[b * (D / 4) + (kt >> 2) + c];
        }
        __syncthreads();

        const float4* wa0p = reinterpret_cast<const float4*>(Wa + (size_t)i0 * D + kt);
        const float4* wa1p = reinterpret_cast<const float4*>(Wa + (size_t)i1 * D + kt);
        const float4* wx0p = reinterpret_cast<const float4*>(Wx + (size_t)i0 * D + kt);
        const float4* wx1p = reinterpret_cast<const float4*>(Wx + (size_t)i1 * D + kt);
        const float4* xbase = xs4 + bg * 8 * 128;

#pragma unroll
        for (int m = 0; m < 4; m++) {
            const int idx = m * 32 + lane;
            float4 wa0 = __ldg(wa0p + idx);
            float4 wa1 = __ldg(wa1p + idx);
            float4 wx0 = __ldg(wx0p + idx);
            float4 wx1 = __ldg(wx1p + idx);
#pragma unroll
            for (int b = 0; b < 8; b++) {
                float4 x = xbase[b * 128 + idx];

                v[b]      = fmaf(wa0.x, x.x, v[b]);
                v[b]      = fmaf(wa0.y, x.y, v[b]);
                v[b]      = fmaf(wa0.z, x.z, v[b]);
                v[b]      = fmaf(wa0.w, x.w, v[b]);

                v[8 + b]  = fmaf(wx0.x, x.x, v[8 + b]);
                v[8 + b]  = fmaf(wx0.y, x.y, v[8 + b]);
                v[8 + b]  = fmaf(wx0.z, x.z, v[8 + b]);
                v[8 + b]  = fmaf(wx0.w, x.w, v[8 + b]);

                v[16 + b] = fmaf(wa1.x, x.x, v[16 + b]);
                v[16 + b] = fmaf(wa1.y, x.y, v[16 + b]);
                v[16 + b] = fmaf(wa1.z, x.z, v[16 + b]);
                v[16 + b] = fmaf(wa1.w, x.w, v[16 + b]);

                v[24 + b] = fmaf(wx1.x, x.x, v[24 + b]);
                v[24 + b] = fmaf(wx1.y, x.y, v[24 + b]);
                v[24 + b] = fmaf(wx1.z, x.z, v[24 + b]);
                v[24 + b] = fmaf(wx1.w, x.w, v[24 + b]);
            }
        }
    }

    treduce32(v, lane);
    float r = v[0];
    float p = __shfl_xor_sync(0xffffffffu, r, 8);   // pair dotA with dotX

    if (lane < 8) {
        finalize_one(bg * 8 + lane, i0, r, p, xt, h, ba, bx, Lam);
    } else if (lane >= 16 && lane < 24) {
        finalize_one(bg * 8 + (lane - 16), i1, r, p, xt, h, ba, bx, Lam);
    }
}

// Gates producer: 64 blocks x 256 threads, 4 items each.
// Phase p produces slices 4p..4p+3 (block bid -> slice 4p + (bid>>4), item bid&15).
__global__ __launch_bounds__(256) void gates_kernel(
    const float* __restrict__ xt, const float* __restrict__ h,
    const float* __restrict__ Wa, const float* __restrict__ Wx,
    const float* __restrict__ ba, const float* __restrict__ bx,
    const float* __restrict__ Lam)
{
    __shared__ float4 xs4[B * 128];   // 32 KB

#if __CUDA_ARCH__ >= 900
    cudaTriggerProgrammaticLaunchCompletion();   // all threads (canonical)
#endif

    const int tid = threadIdx.x;
    const int bid = blockIdx.x;

#pragma unroll 1
    for (int p = 0; p < 4; p++) {
        const int slice = 4 * p + (bid >> 4);
        const int idx   = bid & 15;
        gates_item(slice * 128 + idx * 8, tid, xs4, xt, h, Wa, Wx, ba, bx, Lam);
        __threadfence();        // release: push u/diag to device scope
        __syncthreads();
        if (tid == 0) atomicAdd(&g_ready[slice], 1u);
    }
}

// Writer consumer (launched with PDL): block m -> s = m>>7, b = (m>>3)&15,
// rc = m&7. Writes out[b, rc*256 .. rc*256+256, s*128 .. s*128+128).
__global__ __launch_bounds__(256) void writer_kernel(float* __restrict__ out) {
    const int tid  = threadIdx.x;
    const int lane = tid & 31;
    const int warp = tid >> 5;
    const unsigned m = blockIdx.x;

    const int s  = m >> 7;          // 4 bits: slice
    const int b  = (m >> 3) & 15;   // 4 bits: batch
    const int rc = m & 7;           // 3 bits: 256-row chunk

    if (tid == 0) {
        while (atomicAdd(&g_ready[s], 0u) < 16u) __nanosleep(128);
        __threadfence();            // acquire (observer thread)
    }
    __syncthreads();
    __threadfence();                // acquire fence for all reader threads

    // u segment for this slice: 128 floats, one float4 per lane.
    // __ldcg: coherent L2 load (NOT the non-coherent __ldg path — data was
    // written during this kernel's lifetime by the overlapped producer).
    const float4 uv = __ldcg(reinterpret_cast<const float4*>(
                                 g_u + (size_t)b * D + s * 128) + lane);
    const float* dgb = g_diag + (size_t)b * D;

    const int i_first = rc * 256 + warp;     // rows: i_first + 8*t, t=0..31
    float* rowp = out + ((size_t)b * D + (size_t)i_first) * D + s * 128;
    int i = i_first;

#pragma unroll 4
    for (int t = 0; t < 32; t++) {
        float4 val = uv;
        const int li = i - s * 128;
        if (li >= 0 && li < 128) {            // diagonal element lives in this tile
            if ((li >> 2) == lane) {
                float dv = __ldcg(dgb + i);
                switch (li & 3) {
                    case 0: val.x += dv; break;
                    case 1: val.y += dv; break;
                    case 2: val.z += dv; break;
                    default: val.w += dv; break;
                }
            }
        }
        __stcs(reinterpret_cast<float4*>(rowp) + lane, val);
        rowp += 8 * D;
        i    += 8;
    }

    // Last writer block resets flags for the next graph replay. Ordered before
    // the next replay's gates by normal stream serialization (gates has no PDL).
    __syncthreads();
    if (tid == 0) {
        __threadfence();
        unsigned old = atomicAdd(&g_done, 1u);
        if (old == WGRID - 1) {
#pragma unroll
            for (int k = 0; k < 16; k++) g_ready[k] = 0u;
            g_done = 0u;
            __threadfence();
        }
    }
}

extern "C" void kernel_launch(void* const* d_in, const int* in_sizes, int n_in,
                              void* d_out, int out_size) {
    const float* xt  = (const float*)d_in[0];
    const float* h   = (const float*)d_in[1];
    const float* Wa  = (const float*)d_in[2];
    const float* Wx  = (const float*)d_in[3];
    const float* ba  = (const float*)d_in[4];
    const float* bx  = (const float*)d_in[5];
    const float* Lam = (const float*)d_in[6];

    gates_kernel<<<NGBLK, 256>>>(xt, h, Wa, Wx, ba, bx, Lam);

    // Writer launched with Programmatic Stream Serialization so it can begin
    // while gates is still running; data dependency enforced by g_ready flags.
    cudaLaunchAttribute attr;
    attr.id = cudaLaunchAttributeProgrammaticStreamSerialization;
    attr.val.programmaticStreamSerializationAllowed = 1;

    cudaLaunchConfig_t cfg = {};
    cfg.gridDim  = dim3(WGRID, 1, 1);
    cfg.blockDim = dim3(256, 1, 1);
    cfg.dynamicSmemBytes = 0;
    cfg.stream   = 0;
    cfg.attrs    = &attr;
    cfg.numAttrs = 1;

    float* out = (float*)d_out;
    cudaError_t err = cudaLaunchKernelEx(&cfg, writer_kernel, out);
    if (err != cudaSuccess) {
        // Fallback: plain serialized launch
        writer_kernel<<<WGRID, 256>>>(out);
    }
}

// round 8
// speedup vs baseline: 1.6864x; 1.6864x over previous
#include <cuda_runtime.h>

#define D 2048
#define B 16

// Scratch (allocation-free rule: device globals)
__device__ float g_u[B * D];
__device__ float g_diag[B * D];

__device__ __forceinline__ float sigmoidf(float x) {
    return 1.0f / (1.0f + __expf(-x));
}

// Warp transpose-reduce: lane l ends with (in v[0]) the 32-lane total of
// logical index l.
__device__ __forceinline__ void treduce32(float (&v)[32], int lane) {
#pragma unroll
    for (int m = 16; m > 0; m >>= 1) {
#pragma unroll
        for (int t = 0; t < 16; t++) {
            if (t < m) {
                float lo = v[t];
                float hi = v[t + m];
                float send = (lane & m) ? lo : hi;
                float recv = __shfl_xor_sync(0xffffffffu, send, m);
                v[t] = (lane & m) ? (hi + recv) : (lo + recv);
            }
        }
    }
}

__device__ __forceinline__ void finalize_one(
    int b, int i, float dA, float dX,
    const float* __restrict__ xt, const float* __restrict__ h,
    const float* __restrict__ ba, const float* __restrict__ bx,
    const float* __restrict__ Lam)
{
    float rt = sigmoidf(dA + __ldg(ba + i));
    float it = sigmoidf(dX + __ldg(bx + i));
    float la = -log1pf(__expf(-__ldg(Lam + i)));   // -softplus(-Lam)
    float t  = la * rt * 0.125f;                   // /C, C=8
    float a  = __expf(t);
    float om = -expm1f(2.0f * t);                  // 1 - a^2, cancellation-free
    float u  = sqrtf(fmaxf(om, 0.0f)) * it * __ldg(xt + b * D + i);
    g_u[b * D + i]    = u;
    g_diag[b * D + i] = a * __ldg(h + b * D + i);
}

// Gates with intra-block K-split:
//   Block = 256 threads (8 warps), owns 8 columns [blockIdx.x*8, +8).
//   Warps 0-3: K in [0,1024); warps 4-7: K in [1024,2048).
//   Warp w handles column pair i0 = base + (w&3)*2, i1 = i0+1,
//   BOTH matrices, ALL 16 batches (weights read exactly once).
//   Grid: 256 blocks -> 2048 warps (3.46/SMSP).
__global__ __launch_bounds__(256, 2) void gates_kernel(
    const float* __restrict__ xt, const float* __restrict__ h,
    const float* __restrict__ Wa, const float* __restrict__ Wx,
    const float* __restrict__ ba, const float* __restrict__ bx,
    const float* __restrict__ Lam)
{
    // Two staged xt regions (one per K-half): 2 x 16 x 64 float4 = 32 KB
    __shared__ float4 xs4[2 * B * 64];

    const int tid   = threadIdx.x;
    const int lane  = tid & 31;
    const int warp  = tid >> 5;
    const int kh    = warp >> 2;                 // K-half: 0 or 1
    const int i0    = blockIdx.x * 8 + (warp & 3) * 2;
    const int i1    = i0 + 1;

    // vA: col i0 -> [0..15]=dotA(b), [16..31]=dotX(b). vB: col i1.
    float vA[32], vB[32];
#pragma unroll
    for (int t = 0; t < 32; t++) { vA[t] = 0.0f; vB[t] = 0.0f; }

    const float4* xt4 = reinterpret_cast<const float4*>(xt);

#pragma unroll 1
    for (int kt = 0; kt < 1024; kt += 256) {
        __syncthreads();
        // Stage xt[b, r*1024 + kt .. +256) for r=0,1 (2048 float4, 8/thread)
#pragma unroll
        for (int e = tid; e < 2 * B * 64; e += 256) {
            int r   = e >> 10;           // region (K-half)
            int rem = e & 1023;
            int b   = rem >> 6;
            int c   = rem & 63;
            xs4[e] = xt4[b * (D / 4) + ((r * 1024 + kt) >> 2) + c];
        }
        __syncthreads();

        const int wbase = kh * 1024 + kt;   // this warp's K offset (floats)
        const float4* wa0p = reinterpret_cast<const float4*>(Wa + (size_t)i0 * D + wbase);
        const float4* wa1p = reinterpret_cast<const float4*>(Wa + (size_t)i1 * D + wbase);
        const float4* wx0p = reinterpret_cast<const float4*>(Wx + (size_t)i0 * D + wbase);
        const float4* wx1p = reinterpret_cast<const float4*>(Wx + (size_t)i1 * D + wbase);
        const float4* xbase = xs4 + kh * B * 64;

#pragma unroll
        for (int m = 0; m < 2; m++) {
            const int idx = m * 32 + lane;
            float4 wa0 = __ldg(wa0p + idx);
            float4 wa1 = __ldg(wa1p + idx);
            float4 wx0 = __ldg(wx0p + idx);
            float4 wx1 = __ldg(wx1p + idx);
#pragma unroll
            for (int b = 0; b < 16; b++) {
                float4 x = xbase[b * 64 + idx];

                vA[b]      = fmaf(wa0.x, x.x, vA[b]);
                vA[b]      = fmaf(wa0.y, x.y, vA[b]);
                vA[b]      = fmaf(wa0.z, x.z, vA[b]);
                vA[b]      = fmaf(wa0.w, x.w, vA[b]);

                vA[16 + b] = fmaf(wx0.x, x.x, vA[16 + b]);
                vA[16 + b] = fmaf(wx0.y, x.y, vA[16 + b]);
                vA[16 + b] = fmaf(wx0.z, x.z, vA[16 + b]);
                vA[16 + b] = fmaf(wx0.w, x.w, vA[16 + b]);

                vB[b]      = fmaf(wa1.x, x.x, vB[b]);
                vB[b]      = fmaf(wa1.y, x.y, vB[b]);
                vB[b]      = fmaf(wa1.z, x.z, vB[b]);
                vB[b]      = fmaf(wa1.w, x.w, vB[b]);

                vB[16 + b] = fmaf(wx1.x, x.x, vB[16 + b]);
                vB[16 + b] = fmaf(wx1.y, x.y, vB[16 + b]);
                vB[16 + b] = fmaf(wx1.z, x.z, vB[16 + b]);
                vB[16 + b] = fmaf(wx1.w, x.w, vB[16 + b]);
            }
        }
    }

    treduce32(vA, lane);   // lane l: sum for col i0, mat = l>>4, b = l&15
    treduce32(vB, lane);
    float rA = vA[0], rB = vB[0];

    // Combine the two K-halves through smem (reuse xs4 storage).
    float* sred = reinterpret_cast<float*>(xs4);   // 4 warps x 64 floats
    __syncthreads();                               // everyone done with xs4
    if (kh == 0) {
        sred[(warp & 3) * 64 + lane]      = rA;
        sred[(warp & 3) * 64 + 32 + lane] = rB;
    }
    __syncthreads();
    if (kh == 1) {
        rA += sred[(warp & 3) * 64 + lane];
        rB += sred[(warp & 3) * 64 + 32 + lane];

        float pA = __shfl_xor_sync(0xffffffffu, rA, 16);  // pair dotA <-> dotX
        float pB = __shfl_xor_sync(0xffffffffu, rB, 16);

        if (lane < 16) {
            finalize_one(lane, i0, rA, pA, xt, h, ba, bx, Lam);
            finalize_one(lane, i1, rB, pB, xt, h, ba, bx, Lam);
        }
    }
}

// Writer: ht[b,i,j] = u[b,j] + (i==j)*diag[b,i].
// Block = (batch b, 16 consecutive rows i). u row held in registers
// (2 float4 / thread, 256 threads = 2048 floats). Streaming stores.
__global__ __launch_bounds__(256) void writer_kernel(float* __restrict__ out) {
    const int b   = blockIdx.y;
    const int i0  = blockIdx.x * 16;
    const int tid = threadIdx.x;

    const float4* u4 = reinterpret_cast<const float4*>(g_u + b * D);
    const float4  va = __ldg(u4 + tid);
    const float4  vb = __ldg(u4 + tid + 256);
    const float*  dg = g_diag + b * D;

    float* obase = out + ((size_t)b * D + (size_t)i0) * D;

#pragma unroll 4
    for (int r = 0; r < 16; r++) {
        const int i  = i0 + r;
        const float dv = __ldg(dg + i);
        float4 sa = va, sb = vb;
        const int q = i >> 2, c = i & 3;
        if (q == tid) {
            if      (c == 0) sa.x += dv;
            else if (c == 1) sa.y += dv;
            else if (c == 2) sa.z += dv;
            else             sa.w += dv;
        } else if (q - 256 == tid) {
            if      (c == 0) sb.x += dv;
            else if (c == 1) sb.y += dv;
            else if (c == 2) sb.z += dv;
            else             sb.w += dv;
        }
        float4* orow = reinterpret_cast<float4*>(obase + (size_t)r * D);
        __stcs(orow + tid, sa);
        __stcs(orow + tid + 256, sb);
    }
}

extern "C" void kernel_launch(void* const* d_in, const int* in_sizes, int n_in,
                              void* d_out, int out_size) {
    const float* xt  = (const float*)d_in[0];
    const float* h   = (const float*)d_in[1];
    const float* Wa  = (const float*)d_in[2];
    const float* Wx  = (const float*)d_in[3];
    const float* ba  = (const float*)d_in[4];
    const float* bx  = (const float*)d_in[5];
    const float* Lam = (const float*)d_in[6];

    gates_kernel<<<256, 256>>>(xt, h, Wa, Wx, ba, bx, Lam);

    dim3 grid(D / 16, B);
    writer_kernel<<<grid, 256>>>((float*)d_out);
}